// round 12
// baseline (speedup 1.0000x reference)
#include <cuda_runtime.h>
#include <cstdint>

#define BN_EPS   1e-3f
#define DIN      128
#define DOUT     256
#define MT       96
#define NTHREADS 384

// smem (floats): sW[32768] | sA[12 warps][1024] | sScale[256] | sBias[256]
#define SMEM_FLOATS (32768 + 12288 + 256 + 256)
#define SMEM_BYTES  (SMEM_FLOATS * 4)

__device__ __forceinline__ void ffma2(unsigned long long &d, unsigned long long a, unsigned long long b) {
    asm("fma.rn.f32x2 %0, %1, %2, %0;" : "+l"(d) : "l"(a), "l"(b));
}
__device__ __forceinline__ unsigned long long dup2(float x) {
    unsigned long long r;
    asm("mov.b64 %0, {%1, %1};" : "=l"(r) : "f"(x));
    return r;
}
__device__ __forceinline__ void unpack2(unsigned long long v, float &lo, float &hi) {
    asm("mov.b64 {%0, %1}, %2;" : "=f"(lo), "=f"(hi) : "l"(v));
}
__device__ __forceinline__ void cp_async16(float* dst_smem, const float* src) {
    unsigned s = (unsigned)__cvta_generic_to_shared(dst_smem);
    asm volatile("cp.async.cg.shared.global [%0], [%1], 16;" :: "r"(s), "l"(src));
}
#define CP_COMMIT() asm volatile("cp.async.commit_group;")
#define CP_WAIT0()  asm volatile("cp.async.wait_group 0;")

__global__ __launch_bounds__(NTHREADS, 1)
void attn_transformer_kernel(const float* __restrict__ inputs,
                             const float* __restrict__ priors,
                             const float* __restrict__ W,
                             const float* __restrict__ gamma,
                             const float* __restrict__ beta,
                             const float* __restrict__ mmean,
                             const float* __restrict__ mvar,
                             float* __restrict__ out,
                             int nTiles, int nRows)
{
    extern __shared__ float smem[];
    float* sW     = smem;                    // [128][256]
    float* sAbase = smem + 32768;            // [12 warps][8][128]
    float* sScale = smem + 32768 + 12288;    // [256]
    float* sBias  = sScale + 256;            // [256]

    const int tid   = threadIdx.x;
    const int lane  = tid & 31;
    const int warp  = tid >> 5;
    const int lane4 = lane * 4;

    float* sA = sAbase + warp * 1024;        // this warp's private 8-row buffer

    // ---- prologue ----
    // W -> smem (all threads cooperate; 8192 float4 chunks over 384 threads)
    #pragma unroll
    for (int j = 0; j < 22; ++j) {
        int idx = tid + NTHREADS * j;
        if (idx < 8192) cp_async16(sW + idx * 4, W + idx * 4);
    }
    // this warp's first A rows (8 rows x 128 floats = 256 x 16B chunks)
    {
        size_t r0 = (size_t)blockIdx.x * MT + warp * 8;
        if (r0 < (size_t)nRows) {
            const float* Abase = inputs + r0 * DIN;
            #pragma unroll
            for (int j = 0; j < 8; ++j) {
                int c = lane + 32 * j;
                cp_async16(sA + c * 4, Abase + c * 4);
            }
        }
    }
    CP_COMMIT();

    // fold BN into scale/bias
    if (tid < 256) {
        float inv = gamma[tid] * rsqrtf(mvar[tid] + BN_EPS);
        sScale[tid] = inv;
        sBias[tid]  = beta[tid] - mmean[tid] * inv;
    }

    CP_WAIT0();
    __syncthreads();     // W + consts visible to all warps; the ONLY CTA barrier

    for (int t = blockIdx.x; t < nTiles; t += gridDim.x) {
        const size_t row0 = (size_t)t * MT + warp * 8;
        const bool active = row0 < (size_t)nRows;   // tail tile: warps 8-11 idle

        unsigned long long acc[8][4];
        if (active) {
            // ---- GEMM: 8 rows x 8 cols per thread, packed f32x2 FFMA ----
            #pragma unroll
            for (int i = 0; i < 8; ++i) {
                acc[i][0] = 0ull; acc[i][1] = 0ull; acc[i][2] = 0ull; acc[i][3] = 0ull;
            }

            #pragma unroll 2
            for (int kk = 0; kk < DIN; kk += 4) {
                float4 a4[8];
                #pragma unroll
                for (int i = 0; i < 8; ++i)
                    a4[i] = *reinterpret_cast<const float4*>(&sA[i * DIN + kk]);
                #pragma unroll
                for (int q = 0; q < 4; ++q) {
                    const float* wrow = &sW[(kk + q) * DOUT];
                    ulonglong2 Blo = *reinterpret_cast<const ulonglong2*>(&wrow[lane4]);
                    ulonglong2 Bhi = *reinterpret_cast<const ulonglong2*>(&wrow[128 + lane4]);
                    #pragma unroll
                    for (int i = 0; i < 8; ++i) {
                        float av = (q == 0) ? a4[i].x : (q == 1) ? a4[i].y
                                 : (q == 2) ? a4[i].z : a4[i].w;
                        unsigned long long ad = dup2(av);
                        ffma2(acc[i][0], ad, Blo.x);
                        ffma2(acc[i][1], ad, Blo.y);
                        ffma2(acc[i][2], ad, Bhi.x);
                        ffma2(acc[i][3], ad, Bhi.y);
                    }
                }
            }
        }

        // ---- prefetch next tile's rows into the SAME buffer (GEMM reads done);
        //      epilogue covers the flight; per-warp, no barrier ----
        {
            int tn = t + gridDim.x;
            if (tn < nTiles) {
                size_t rn = (size_t)tn * MT + warp * 8;
                if (rn < (size_t)nRows) {
                    const float* Abase = inputs + rn * DIN;
                    #pragma unroll
                    for (int j = 0; j < 8; ++j) {
                        int c = lane + 32 * j;
                        cp_async16(sA + c * 4, Abase + c * 4);
                    }
                }
            }
            CP_COMMIT();
        }

        // ---- epilogue: stream 4 row-pairs (keeps live registers low) ----
        if (active) {
            #pragma unroll 1
            for (int pr = 0; pr < 4; ++pr) {
                const int iA = 2 * pr, iB = 2 * pr + 1;

                float4 scLo = *reinterpret_cast<const float4*>(&sScale[lane4]);
                float4 scHi = *reinterpret_cast<const float4*>(&sScale[128 + lane4]);
                float4 bLo  = *reinterpret_cast<const float4*>(&sBias[lane4]);
                float4 bHi  = *reinterpret_cast<const float4*>(&sBias[128 + lane4]);

                const float* prA = priors + (row0 + iA) * DOUT;
                const float* prB = priors + (row0 + iB) * DOUT;
                float4 pA0 = *reinterpret_cast<const float4*>(&prA[lane4]);
                float4 pA1 = *reinterpret_cast<const float4*>(&prA[128 + lane4]);
                float4 pB0 = *reinterpret_cast<const float4*>(&prB[lane4]);
                float4 pB1 = *reinterpret_cast<const float4*>(&prB[128 + lane4]);

                float za[8], zb[8];
                {
                    float x0, x1, x2, x3, x4, x5, x6, x7;
                    unpack2(acc[iA][0], x0, x1);
                    unpack2(acc[iA][1], x2, x3);
                    unpack2(acc[iA][2], x4, x5);
                    unpack2(acc[iA][3], x6, x7);
                    za[0] = fmaf(x0, scLo.x, bLo.x) * pA0.x;
                    za[1] = fmaf(x1, scLo.y, bLo.y) * pA0.y;
                    za[2] = fmaf(x2, scLo.z, bLo.z) * pA0.z;
                    za[3] = fmaf(x3, scLo.w, bLo.w) * pA0.w;
                    za[4] = fmaf(x4, scHi.x, bHi.x) * pA1.x;
                    za[5] = fmaf(x5, scHi.y, bHi.y) * pA1.y;
                    za[6] = fmaf(x6, scHi.z, bHi.z) * pA1.z;
                    za[7] = fmaf(x7, scHi.w, bHi.w) * pA1.w;
                    unpack2(acc[iB][0], x0, x1);
                    unpack2(acc[iB][1], x2, x3);
                    unpack2(acc[iB][2], x4, x5);
                    unpack2(acc[iB][3], x6, x7);
                    zb[0] = fmaf(x0, scLo.x, bLo.x) * pB0.x;
                    zb[1] = fmaf(x1, scLo.y, bLo.y) * pB0.y;
                    zb[2] = fmaf(x2, scLo.z, bLo.z) * pB0.z;
                    zb[3] = fmaf(x3, scLo.w, bLo.w) * pB0.w;
                    zb[4] = fmaf(x4, scHi.x, bHi.x) * pB1.x;
                    zb[5] = fmaf(x5, scHi.y, bHi.y) * pB1.y;
                    zb[6] = fmaf(x6, scHi.z, bHi.z) * pB1.z;
                    zb[7] = fmaf(x7, scHi.w, bHi.w) * pB1.w;
                }

                // Michelot fixed point (two rows pipelined through the shfl chains)
                float sa = 0.f, sb = 0.f;
                #pragma unroll
                for (int j = 0; j < 8; ++j) { sa += za[j]; sb += zb[j]; }
                #pragma unroll
                for (int off = 16; off > 0; off >>= 1) {
                    sa += __shfl_xor_sync(0xffffffffu, sa, off);
                    sb += __shfl_xor_sync(0xffffffffu, sb, off);
                }
                float taua = (sa - 1.0f) * (1.0f / 256.0f);
                float taub = (sb - 1.0f) * (1.0f / 256.0f);
                float ca = 256.0f, cb = 256.0f;
                bool da = false, db = false;

                for (int it = 0; it < 64; ++it) {
                    float psa = 0.f, pca = 0.f, psb = 0.f, pcb = 0.f;
                    #pragma unroll
                    for (int j = 0; j < 8; ++j) {
                        if (za[j] > taua) { psa += za[j]; pca += 1.0f; }
                        if (zb[j] > taub) { psb += zb[j]; pcb += 1.0f; }
                    }
                    #pragma unroll
                    for (int off = 16; off > 0; off >>= 1) {
                        psa += __shfl_xor_sync(0xffffffffu, psa, off);
                        pca += __shfl_xor_sync(0xffffffffu, pca, off);
                        psb += __shfl_xor_sync(0xffffffffu, psb, off);
                        pcb += __shfl_xor_sync(0xffffffffu, pcb, off);
                    }
                    if (!da) {
                        if (pca == ca) da = true;
                        else { ca = pca; taua = (psa - 1.0f) / pca; }
                    }
                    if (!db) {
                        if (pcb == cb) db = true;
                        else { cb = pcb; taub = (psb - 1.0f) / pcb; }
                    }
                    if (da && db) break;
                }

                float* o0 = out + (row0 + iA) * DOUT;
                float* o1 = out + (row0 + iB) * DOUT;
                float4 v;
                v.x = fmaxf(za[0] - taua, 0.f); v.y = fmaxf(za[1] - taua, 0.f);
                v.z = fmaxf(za[2] - taua, 0.f); v.w = fmaxf(za[3] - taua, 0.f);
                *reinterpret_cast<float4*>(&o0[lane4]) = v;
                v.x = fmaxf(za[4] - taua, 0.f); v.y = fmaxf(za[5] - taua, 0.f);
                v.z = fmaxf(za[6] - taua, 0.f); v.w = fmaxf(za[7] - taua, 0.f);
                *reinterpret_cast<float4*>(&o0[128 + lane4]) = v;
                v.x = fmaxf(zb[0] - taub, 0.f); v.y = fmaxf(zb[1] - taub, 0.f);
                v.z = fmaxf(zb[2] - taub, 0.f); v.w = fmaxf(zb[3] - taub, 0.f);
                *reinterpret_cast<float4*>(&o1[lane4]) = v;
                v.x = fmaxf(zb[4] - taub, 0.f); v.y = fmaxf(zb[5] - taub, 0.f);
                v.z = fmaxf(zb[6] - taub, 0.f); v.w = fmaxf(zb[7] - taub, 0.f);
                *reinterpret_cast<float4*>(&o1[128 + lane4]) = v;
            }
        }

        // wait for this warp's prefetch before the next GEMM reads sA
        CP_WAIT0();
        __syncwarp();
    }
}

extern "C" void kernel_launch(void* const* d_in, const int* in_sizes, int n_in,
                              void* d_out, int out_size) {
    const float* inputs = (const float*)d_in[0];
    const float* priors = (const float*)d_in[1];
    const float* W      = (const float*)d_in[2];
    const float* gamma  = (const float*)d_in[3];
    const float* beta   = (const float*)d_in[4];
    const float* mmean  = (const float*)d_in[5];
    const float* mvar   = (const float*)d_in[6];
    float* out = (float*)d_out;

    int nRows  = in_sizes[0] / DIN;              // 262144
    int nTiles = (nRows + MT - 1) / MT;          // 2731 (tail tile = 64 rows)

    int dev = 0;
    cudaGetDevice(&dev);
    int nsm = 0;
    cudaDeviceGetAttribute(&nsm, cudaDevAttrMultiProcessorCount, dev);
    if (nsm <= 0) nsm = 148;
    if (nsm > nTiles) nsm = nTiles;

    cudaFuncSetAttribute(attn_transformer_kernel,
                         cudaFuncAttributeMaxDynamicSharedMemorySize, SMEM_BYTES);

    attn_transformer_kernel<<<nsm, NTHREADS, SMEM_BYTES>>>(
        inputs, priors, W, gamma, beta, mmean, mvar, out, nTiles, nRows);
}

// round 13
// speedup vs baseline: 1.3469x; 1.3469x over previous
#include <cuda_runtime.h>
#include <cstdint>

#define BN_EPS   1e-3f
#define DIN      128
#define DOUT     256
#define MT       64
#define NTHREADS 256

// smem (floats): sW[32768] | sA[8 warps][2 bufs][1024] | sScale[256] | sBias[256]
#define SMEM_FLOATS (32768 + 16384 + 256 + 256)
#define SMEM_BYTES  (SMEM_FLOATS * 4)

__device__ __forceinline__ void ffma2(unsigned long long &d, unsigned long long a, unsigned long long b) {
    asm("fma.rn.f32x2 %0, %1, %2, %0;" : "+l"(d) : "l"(a), "l"(b));
}
__device__ __forceinline__ unsigned long long dup2(float x) {
    unsigned long long r;
    asm("mov.b64 %0, {%1, %1};" : "=l"(r) : "f"(x));
    return r;
}
__device__ __forceinline__ void unpack2(unsigned long long v, float &lo, float &hi) {
    asm("mov.b64 {%0, %1}, %2;" : "=f"(lo), "=f"(hi) : "l"(v));
}
__device__ __forceinline__ void cp_async16(float* dst_smem, const float* src) {
    unsigned s = (unsigned)__cvta_generic_to_shared(dst_smem);
    asm volatile("cp.async.cg.shared.global [%0], [%1], 16;" :: "r"(s), "l"(src));
}
#define CP_COMMIT() asm volatile("cp.async.commit_group;")
#define CP_WAIT1()  asm volatile("cp.async.wait_group 1;")

__global__ __launch_bounds__(NTHREADS, 1)
void attn_transformer_kernel(const float* __restrict__ inputs,
                             const float* __restrict__ priors,
                             const float* __restrict__ W,
                             const float* __restrict__ gamma,
                             const float* __restrict__ beta,
                             const float* __restrict__ mmean,
                             const float* __restrict__ mvar,
                             float* __restrict__ out,
                             int nTiles)
{
    extern __shared__ float smem[];
    float* sW     = smem;                    // [128][256]
    float* sAbase = smem + 32768;            // [8 warps][2][8][128]
    float* sScale = smem + 32768 + 16384;    // [256]
    float* sBias  = sScale + 256;            // [256]

    const int tid   = threadIdx.x;
    const int lane  = tid & 31;
    const int warp  = tid >> 5;
    const int lane4 = lane * 4;

    float* sA0 = sAbase + warp * 2048;       // this warp's buffer 0
    float* sA1 = sA0 + 1024;                 // buffer 1

    // ---- prologue ----
    // group g0: W -> smem (all threads cooperate)
    #pragma unroll
    for (int j = 0; j < 32; ++j) {
        int idx = tid + NTHREADS * j;                // float4 idx [0,8192)
        cp_async16(sW + idx * 4, W + idx * 4);
    }
    CP_COMMIT();
    // group g1: this warp's first A tile (8 rows x 128 floats)
    {
        const float* Abase = inputs + ((size_t)blockIdx.x * MT + warp * 8) * DIN;
        #pragma unroll
        for (int j = 0; j < 8; ++j) {
            int c = lane + 32 * j;
            cp_async16(sA0 + c * 4, Abase + c * 4);
        }
    }
    CP_COMMIT();

    // fold BN into scale/bias
    {
        float inv = gamma[tid] * rsqrtf(mvar[tid] + BN_EPS);
        sScale[tid] = inv;
        sBias[tid]  = beta[tid] - mmean[tid] * inv;
    }

    CP_WAIT1();
    __syncthreads();     // W + consts visible; the ONLY CTA barrier

    // loop-invariant epilogue constants
    float4 scLo = *reinterpret_cast<const float4*>(&sScale[lane4]);
    float4 scHi = *reinterpret_cast<const float4*>(&sScale[128 + lane4]);
    float4 bLo  = *reinterpret_cast<const float4*>(&sBias[lane4]);
    float4 bHi  = *reinterpret_cast<const float4*>(&sBias[128 + lane4]);

    const float* wpl = sW + lane4;          // lane's low-128 column group
    const float* wph = sW + 128 + lane4;    // lane's high-128 column group

    int p = 0;
    for (int t = blockIdx.x; t < nTiles; t += gridDim.x) {
        // prefetch this warp's rows of the next tile into the other buffer
        int tn = t + gridDim.x;
        if (tn < nTiles) {
            float* sAn = p ? sA0 : sA1;
            const float* Abase = inputs + ((size_t)tn * MT + warp * 8) * DIN;
            #pragma unroll
            for (int j = 0; j < 8; ++j) {
                int c = lane + 32 * j;
                cp_async16(sAn + c * 4, Abase + c * 4);
            }
        }
        CP_COMMIT();
        CP_WAIT1();                          // current tile's copies done (per-warp)
        __syncwarp();

        const float* sA = p ? sA1 : sA0;

        // ---- GEMM: 8 rows x 8 cols per thread, explicit 2-stage register pipeline ----
        unsigned long long acc[8][4];
        #pragma unroll
        for (int i = 0; i < 8; ++i) {
            acc[i][0] = 0ull; acc[i][1] = 0ull; acc[i][2] = 0ull; acc[i][3] = 0ull;
        }

        float4 ac[8], an[8];
        ulonglong2 wlc[4], whc[4], wln[4], whn[4];

        // preload stage for kk = 0
        #pragma unroll
        for (int i = 0; i < 8; ++i)
            ac[i] = *reinterpret_cast<const float4*>(&sA[i * DIN]);
        #pragma unroll
        for (int q = 0; q < 4; ++q) {
            wlc[q] = *reinterpret_cast<const ulonglong2*>(&wpl[q * DOUT]);
            whc[q] = *reinterpret_cast<const ulonglong2*>(&wph[q * DOUT]);
        }

        #define COMPUTE(AREG, WL, WH)                                          \
            _Pragma("unroll")                                                  \
            for (int q = 0; q < 4; ++q) {                                      \
                _Pragma("unroll")                                              \
                for (int i = 0; i < 8; ++i) {                                  \
                    float av = (q == 0) ? AREG[i].x : (q == 1) ? AREG[i].y     \
                             : (q == 2) ? AREG[i].z : AREG[i].w;               \
                    unsigned long long ad = dup2(av);                          \
                    ffma2(acc[i][0], ad, WL[q].x);                             \
                    ffma2(acc[i][1], ad, WL[q].y);                             \
                    ffma2(acc[i][2], ad, WH[q].x);                             \
                    ffma2(acc[i][3], ad, WH[q].y);                             \
                }                                                              \
            }

        #pragma unroll 1
        for (int kk = 0; kk < DIN; kk += 8) {
            // issue loads for stage kk+4 before computing stage kk
            #pragma unroll
            for (int i = 0; i < 8; ++i)
                an[i] = *reinterpret_cast<const float4*>(&sA[i * DIN + kk + 4]);
            #pragma unroll
            for (int q = 0; q < 4; ++q) {
                wln[q] = *reinterpret_cast<const ulonglong2*>(&wpl[(kk + 4 + q) * DOUT]);
                whn[q] = *reinterpret_cast<const ulonglong2*>(&wph[(kk + 4 + q) * DOUT]);
            }
            COMPUTE(ac, wlc, whc);

            // issue loads for stage kk+8 (guarded) before computing stage kk+4
            if (kk + 8 < DIN) {
                #pragma unroll
                for (int i = 0; i < 8; ++i)
                    ac[i] = *reinterpret_cast<const float4*>(&sA[i * DIN + kk + 8]);
                #pragma unroll
                for (int q = 0; q < 4; ++q) {
                    wlc[q] = *reinterpret_cast<const ulonglong2*>(&wpl[(kk + 8 + q) * DOUT]);
                    whc[q] = *reinterpret_cast<const ulonglong2*>(&wph[(kk + 8 + q) * DOUT]);
                }
            }
            COMPUTE(an, wln, whn);
        }
        #undef COMPUTE

        // ---- epilogue: BN + prior mask ----
        const size_t row0 = (size_t)t * MT + warp * 8;

        float4 P[8][2];
        #pragma unroll
        for (int i = 0; i < 8; ++i) {
            const float* pr = priors + (row0 + i) * DOUT;
            P[i][0] = *reinterpret_cast<const float4*>(&pr[lane4]);
            P[i][1] = *reinterpret_cast<const float4*>(&pr[128 + lane4]);
        }

        float z[8][8];
        #pragma unroll
        for (int i = 0; i < 8; ++i) {
            float x0, x1, x2, x3, x4, x5, x6, x7;
            unpack2(acc[i][0], x0, x1);
            unpack2(acc[i][1], x2, x3);
            unpack2(acc[i][2], x4, x5);
            unpack2(acc[i][3], x6, x7);
            z[i][0] = fmaf(x0, scLo.x, bLo.x) * P[i][0].x;
            z[i][1] = fmaf(x1, scLo.y, bLo.y) * P[i][0].y;
            z[i][2] = fmaf(x2, scLo.z, bLo.z) * P[i][0].z;
            z[i][3] = fmaf(x3, scLo.w, bLo.w) * P[i][0].w;
            z[i][4] = fmaf(x4, scHi.x, bHi.x) * P[i][1].x;
            z[i][5] = fmaf(x5, scHi.y, bHi.y) * P[i][1].y;
            z[i][6] = fmaf(x6, scHi.z, bHi.z) * P[i][1].z;
            z[i][7] = fmaf(x7, scHi.w, bHi.w) * P[i][1].w;
        }

        // ---- sparsemax (Michelot fixed point), rows in pairs ----
        #pragma unroll
        for (int i = 0; i < 8; i += 2) {
            float* za = z[i];
            float* zb = z[i + 1];

            float sa = 0.f, sb = 0.f;
            #pragma unroll
            for (int j = 0; j < 8; ++j) { sa += za[j]; sb += zb[j]; }
            #pragma unroll
            for (int off = 16; off > 0; off >>= 1) {
                sa += __shfl_xor_sync(0xffffffffu, sa, off);
                sb += __shfl_xor_sync(0xffffffffu, sb, off);
            }
            float taua = (sa - 1.0f) * (1.0f / 256.0f);
            float taub = (sb - 1.0f) * (1.0f / 256.0f);
            float ca = 256.0f, cb = 256.0f;
            bool da = false, db = false;

            for (int it = 0; it < 64; ++it) {
                float psa = 0.f, pca = 0.f, psb = 0.f, pcb = 0.f;
                #pragma unroll
                for (int j = 0; j < 8; ++j) {
                    if (za[j] > taua) { psa += za[j]; pca += 1.0f; }
                    if (zb[j] > taub) { psb += zb[j]; pcb += 1.0f; }
                }
                #pragma unroll
                for (int off = 16; off > 0; off >>= 1) {
                    psa += __shfl_xor_sync(0xffffffffu, psa, off);
                    pca += __shfl_xor_sync(0xffffffffu, pca, off);
                    psb += __shfl_xor_sync(0xffffffffu, psb, off);
                    pcb += __shfl_xor_sync(0xffffffffu, pcb, off);
                }
                if (!da) {
                    if (pca == ca) da = true;
                    else { ca = pca; taua = (psa - 1.0f) / pca; }
                }
                if (!db) {
                    if (pcb == cb) db = true;
                    else { cb = pcb; taub = (psb - 1.0f) / pcb; }
                }
                if (da && db) break;
            }

            float* o0 = out + (row0 + i) * DOUT;
            float* o1 = out + (row0 + i + 1) * DOUT;
            float4 v;
            v.x = fmaxf(za[0] - taua, 0.f); v.y = fmaxf(za[1] - taua, 0.f);
            v.z = fmaxf(za[2] - taua, 0.f); v.w = fmaxf(za[3] - taua, 0.f);
            *reinterpret_cast<float4*>(&o0[lane4]) = v;
            v.x = fmaxf(za[4] - taua, 0.f); v.y = fmaxf(za[5] - taua, 0.f);
            v.z = fmaxf(za[6] - taua, 0.f); v.w = fmaxf(za[7] - taua, 0.f);
            *reinterpret_cast<float4*>(&o0[128 + lane4]) = v;
            v.x = fmaxf(zb[0] - taub, 0.f); v.y = fmaxf(zb[1] - taub, 0.f);
            v.z = fmaxf(zb[2] - taub, 0.f); v.w = fmaxf(zb[3] - taub, 0.f);
            *reinterpret_cast<float4*>(&o1[lane4]) = v;
            v.x = fmaxf(zb[4] - taub, 0.f); v.y = fmaxf(zb[5] - taub, 0.f);
            v.z = fmaxf(zb[6] - taub, 0.f); v.w = fmaxf(zb[7] - taub, 0.f);
            *reinterpret_cast<float4*>(&o1[128 + lane4]) = v;
        }

        p ^= 1;
    }
}

extern "C" void kernel_launch(void* const* d_in, const int* in_sizes, int n_in,
                              void* d_out, int out_size) {
    const float* inputs = (const float*)d_in[0];
    const float* priors = (const float*)d_in[1];
    const float* W      = (const float*)d_in[2];
    const float* gamma  = (const float*)d_in[3];
    const float* beta   = (const float*)d_in[4];
    const float* mmean  = (const float*)d_in[5];
    const float* mvar   = (const float*)d_in[6];
    float* out = (float*)d_out;

    int B = in_sizes[0] / DIN;          // 262144
    int nTiles = B / MT;                // 4096

    int dev = 0;
    cudaGetDevice(&dev);
    int nsm = 0;
    cudaDeviceGetAttribute(&nsm, cudaDevAttrMultiProcessorCount, dev);
    if (nsm <= 0) nsm = 148;
    if (nsm > nTiles) nsm = nTiles;

    cudaFuncSetAttribute(attn_transformer_kernel,
                         cudaFuncAttributeMaxDynamicSharedMemorySize, SMEM_BYTES);

    attn_transformer_kernel<<<nsm, NTHREADS, SMEM_BYTES>>>(
        inputs, priors, W, gamma, beta, mmean, mvar, out, nTiles);
}

// round 15
// speedup vs baseline: 1.3603x; 1.0099x over previous
#include <cuda_runtime.h>
#include <cstdint>

#define BN_EPS   1e-3f
#define DIN      128
#define DOUT     256
#define MT       64
#define NTHREADS 256

// smem (floats): sW[32768] | sA[8 warps][2 bufs][1024] | sScale[256] | sBias[256]
#define SMEM_FLOATS (32768 + 16384 + 256 + 256)
#define SMEM_BYTES  (SMEM_FLOATS * 4)

__device__ __forceinline__ void ffma2(unsigned long long &d, unsigned long long a, unsigned long long b) {
    asm("fma.rn.f32x2 %0, %1, %2, %0;" : "+l"(d) : "l"(a), "l"(b));
}
__device__ __forceinline__ unsigned long long dup2(float x) {
    unsigned long long r;
    asm("mov.b64 %0, {%1, %1};" : "=l"(r) : "f"(x));
    return r;
}
__device__ __forceinline__ void unpack2(unsigned long long v, float &lo, float &hi) {
    asm("mov.b64 {%0, %1}, %2;" : "=f"(lo), "=f"(hi) : "l"(v));
}
__device__ __forceinline__ void cp_async16(float* dst_smem, const float* src) {
    unsigned s = (unsigned)__cvta_generic_to_shared(dst_smem);
    asm volatile("cp.async.cg.shared.global [%0], [%1], 16;" :: "r"(s), "l"(src));
}
#define CP_COMMIT() asm volatile("cp.async.commit_group;")
#define CP_WAIT1()  asm volatile("cp.async.wait_group 1;")

// ---- GEMM: 8 rows x 8 cols per thread, packed f32x2 FFMA (R7-proven) ----
__device__ __forceinline__ void do_gemm(unsigned long long acc[8][4],
                                        const float* __restrict__ sA,
                                        const float* __restrict__ sW,
                                        int lane4)
{
    #pragma unroll
    for (int i = 0; i < 8; ++i) {
        acc[i][0] = 0ull; acc[i][1] = 0ull; acc[i][2] = 0ull; acc[i][3] = 0ull;
    }
    #pragma unroll 2
    for (int kk = 0; kk < DIN; kk += 4) {
        float4 a4[8];
        #pragma unroll
        for (int i = 0; i < 8; ++i)
            a4[i] = *reinterpret_cast<const float4*>(&sA[i * DIN + kk]);
        #pragma unroll
        for (int q = 0; q < 4; ++q) {
            const float* wrow = &sW[(kk + q) * DOUT];
            ulonglong2 Blo = *reinterpret_cast<const ulonglong2*>(&wrow[lane4]);
            ulonglong2 Bhi = *reinterpret_cast<const ulonglong2*>(&wrow[128 + lane4]);
            #pragma unroll
            for (int i = 0; i < 8; ++i) {
                float av = (q == 0) ? a4[i].x : (q == 1) ? a4[i].y
                         : (q == 2) ? a4[i].z : a4[i].w;
                unsigned long long ad = dup2(av);
                ffma2(acc[i][0], ad, Blo.x);
                ffma2(acc[i][1], ad, Blo.y);
                ffma2(acc[i][2], ad, Bhi.x);
                ffma2(acc[i][3], ad, Bhi.y);
            }
        }
    }
}

// ---- epilogue: BN + prior mask + sparsemax + store (R7-proven) ----
__device__ __forceinline__ void do_epi(unsigned long long acc[8][4], size_t row0,
                                       const float* __restrict__ priors,
                                       float* __restrict__ out,
                                       float4 scLo, float4 scHi, float4 bLo, float4 bHi,
                                       int lane4)
{
    float4 P[8][2];
    #pragma unroll
    for (int i = 0; i < 8; ++i) {
        const float* pr = priors + (row0 + i) * DOUT;
        P[i][0] = *reinterpret_cast<const float4*>(&pr[lane4]);
        P[i][1] = *reinterpret_cast<const float4*>(&pr[128 + lane4]);
    }

    float z[8][8];
    #pragma unroll
    for (int i = 0; i < 8; ++i) {
        float x0, x1, x2, x3, x4, x5, x6, x7;
        unpack2(acc[i][0], x0, x1);
        unpack2(acc[i][1], x2, x3);
        unpack2(acc[i][2], x4, x5);
        unpack2(acc[i][3], x6, x7);
        z[i][0] = fmaf(x0, scLo.x, bLo.x) * P[i][0].x;
        z[i][1] = fmaf(x1, scLo.y, bLo.y) * P[i][0].y;
        z[i][2] = fmaf(x2, scLo.z, bLo.z) * P[i][0].z;
        z[i][3] = fmaf(x3, scLo.w, bLo.w) * P[i][0].w;
        z[i][4] = fmaf(x4, scHi.x, bHi.x) * P[i][1].x;
        z[i][5] = fmaf(x5, scHi.y, bHi.y) * P[i][1].y;
        z[i][6] = fmaf(x6, scHi.z, bHi.z) * P[i][1].z;
        z[i][7] = fmaf(x7, scHi.w, bHi.w) * P[i][1].w;
    }

    #pragma unroll
    for (int i = 0; i < 8; i += 2) {
        float* za = z[i];
        float* zb = z[i + 1];

        float sa = 0.f, sb = 0.f;
        #pragma unroll
        for (int j = 0; j < 8; ++j) { sa += za[j]; sb += zb[j]; }
        #pragma unroll
        for (int off = 16; off > 0; off >>= 1) {
            sa += __shfl_xor_sync(0xffffffffu, sa, off);
            sb += __shfl_xor_sync(0xffffffffu, sb, off);
        }
        float taua = (sa - 1.0f) * (1.0f / 256.0f);
        float taub = (sb - 1.0f) * (1.0f / 256.0f);
        float ca = 256.0f, cb = 256.0f;
        bool da = false, db = false;

        for (int it = 0; it < 64; ++it) {
            float psa = 0.f, pca = 0.f, psb = 0.f, pcb = 0.f;
            #pragma unroll
            for (int j = 0; j < 8; ++j) {
                if (za[j] > taua) { psa += za[j]; pca += 1.0f; }
                if (zb[j] > taub) { psb += zb[j]; pcb += 1.0f; }
            }
            #pragma unroll
            for (int off = 16; off > 0; off >>= 1) {
                psa += __shfl_xor_sync(0xffffffffu, psa, off);
                pca += __shfl_xor_sync(0xffffffffu, pca, off);
                psb += __shfl_xor_sync(0xffffffffu, psb, off);
                pcb += __shfl_xor_sync(0xffffffffu, pcb, off);
            }
            if (!da) {
                if (pca == ca) da = true;
                else { ca = pca; taua = (psa - 1.0f) / pca; }
            }
            if (!db) {
                if (pcb == cb) db = true;
                else { cb = pcb; taub = (psb - 1.0f) / pcb; }
            }
            if (da && db) break;
        }

        float* o0 = out + (row0 + i) * DOUT;
        float* o1 = out + (row0 + i + 1) * DOUT;
        float4 v;
        v.x = fmaxf(za[0] - taua, 0.f); v.y = fmaxf(za[1] - taua, 0.f);
        v.z = fmaxf(za[2] - taua, 0.f); v.w = fmaxf(za[3] - taua, 0.f);
        *reinterpret_cast<float4*>(&o0[lane4]) = v;
        v.x = fmaxf(za[4] - taua, 0.f); v.y = fmaxf(za[5] - taua, 0.f);
        v.z = fmaxf(za[6] - taua, 0.f); v.w = fmaxf(za[7] - taua, 0.f);
        *reinterpret_cast<float4*>(&o0[128 + lane4]) = v;
        v.x = fmaxf(zb[0] - taub, 0.f); v.y = fmaxf(zb[1] - taub, 0.f);
        v.z = fmaxf(zb[2] - taub, 0.f); v.w = fmaxf(zb[3] - taub, 0.f);
        *reinterpret_cast<float4*>(&o1[lane4]) = v;
        v.x = fmaxf(zb[4] - taub, 0.f); v.y = fmaxf(zb[5] - taub, 0.f);
        v.z = fmaxf(zb[6] - taub, 0.f); v.w = fmaxf(zb[7] - taub, 0.f);
        *reinterpret_cast<float4*>(&o1[128 + lane4]) = v;
    }
}

__global__ __launch_bounds__(NTHREADS, 1)
void attn_transformer_kernel(const float* __restrict__ inputs,
                             const float* __restrict__ priors,
                             const float* __restrict__ W,
                             const float* __restrict__ gamma,
                             const float* __restrict__ beta,
                             const float* __restrict__ mmean,
                             const float* __restrict__ mvar,
                             float* __restrict__ out,
                             int nTiles)
{
    extern __shared__ float smem[];
    float* sW     = smem;                    // [128][256]
    float* sAbase = smem + 32768;            // [8 warps][2][8][128]
    float* sScale = smem + 32768 + 16384;    // [256]
    float* sBias  = sScale + 256;            // [256]

    const int tid   = threadIdx.x;
    const int lane  = tid & 31;
    const int warp  = tid >> 5;
    const int lane4 = lane * 4;
    const bool oddw = (warp & 1) != 0;

    float* sA0 = sAbase + warp * 2048;       // this warp's buffer 0
    float* sA1 = sA0 + 1024;                 // buffer 1

    // ---- prologue ----
    #pragma unroll
    for (int j = 0; j < 32; ++j) {
        int idx = tid + NTHREADS * j;                // float4 idx [0,8192)
        cp_async16(sW + idx * 4, W + idx * 4);
    }
    CP_COMMIT();
    {
        const float* Abase = inputs + ((size_t)blockIdx.x * MT + warp * 8) * DIN;
        #pragma unroll
        for (int j = 0; j < 8; ++j) {
            int c = lane + 32 * j;
            cp_async16(sA0 + c * 4, Abase + c * 4);
        }
    }
    CP_COMMIT();

    {
        float inv = gamma[tid] * rsqrtf(mvar[tid] + BN_EPS);
        sScale[tid] = inv;
        sBias[tid]  = beta[tid] - mmean[tid] * inv;
    }

    CP_WAIT1();
    __syncthreads();     // W + consts visible; the ONLY CTA barrier

    float4 scLo = *reinterpret_cast<const float4*>(&sScale[lane4]);
    float4 scHi = *reinterpret_cast<const float4*>(&sScale[128 + lane4]);
    float4 bLo  = *reinterpret_cast<const float4*>(&sBias[lane4]);
    float4 bHi  = *reinterpret_cast<const float4*>(&sBias[128 + lane4]);

    unsigned long long acc[8][4];
    size_t pendRow0 = 0;                     // odd warps: row0 of acc awaiting EPI
    bool   pend = false;

    int p = 0;
    for (int t = blockIdx.x; t < nTiles; t += gridDim.x) {
        // odd warps: drain previous tile's epilogue FIRST (overlaps even warps' GEMM)
        if (oddw && pend) {
            do_epi(acc, pendRow0, priors, out, scLo, scHi, bLo, bHi, lane4);
        }

        // prefetch next tile's rows into the other buffer, then wait for current
        int tn = t + gridDim.x;
        if (tn < nTiles) {
            float* sAn = p ? sA0 : sA1;
            const float* Abase = inputs + ((size_t)tn * MT + warp * 8) * DIN;
            #pragma unroll
            for (int j = 0; j < 8; ++j) {
                int c = lane + 32 * j;
                cp_async16(sAn + c * 4, Abase + c * 4);
            }
        }
        CP_COMMIT();
        CP_WAIT1();
        __syncwarp();

        const float* sA = p ? sA1 : sA0;
        do_gemm(acc, sA, sW, lane4);

        const size_t row0 = (size_t)t * MT + warp * 8;
        if (oddw) {
            pendRow0 = row0;                 // defer EPI to next iteration
            pend = true;
        } else {
            do_epi(acc, row0, priors, out, scLo, scHi, bLo, bHi, lane4);
        }

        p ^= 1;
    }

    // odd warps: final deferred epilogue
    if (oddw && pend) {
        do_epi(acc, pendRow0, priors, out, scLo, scHi, bLo, bHi, lane4);
    }
}

extern "C" void kernel_launch(void* const* d_in, const int* in_sizes, int n_in,
                              void* d_out, int out_size) {
    const float* inputs = (const float*)d_in[0];
    const float* priors = (const float*)d_in[1];
    const float* W      = (const float*)d_in[2];
    const float* gamma  = (const float*)d_in[3];
    const float* beta   = (const float*)d_in[4];
    const float* mmean  = (const float*)d_in[5];
    const float* mvar   = (const float*)d_in[6];
    float* out = (float*)d_out;

    int B = in_sizes[0] / DIN;          // 262144
    int nTiles = B / MT;                // 4096

    int dev = 0;
    cudaGetDevice(&dev);
    int nsm = 0;
    cudaDeviceGetAttribute(&nsm, cudaDevAttrMultiProcessorCount, dev);
    if (nsm <= 0) nsm = 148;
    if (nsm > nTiles) nsm = nTiles;

    cudaFuncSetAttribute(attn_transformer_kernel,
                         cudaFuncAttributeMaxDynamicSharedMemorySize, SMEM_BYTES);

    attn_transformer_kernel<<<nsm, NTHREADS, SMEM_BYTES>>>(
        inputs, priors, W, gamma, beta, mmean, mvar, out, nTiles);
}